// round 14
// baseline (speedup 1.0000x reference)
#include <cuda_runtime.h>
#include <cuda_fp16.h>
#include <cstdint>

// Causal SDPA: B=2, H=16, S=2048, D=128, fp32 in/out.
// R14: R13's skewed pipeline (PV(j) + QK(j+2) + softmax(j+1) in one block)
// with the register copies eliminated via x2 unrolled ping-pong buffer sets
// (sA/sB, paA/paB role-swap) -> no spills (R13 hit the 255-reg cap).
//   - K ring 4 stages (&3), V ring 2 stages (&1): no % in hot loop
//   - P in registers (S C-frags == PV A-frags), base-2 ex2 softmax
//   - fp16 m16n8k16 mma w/ f32 accum, ldmatrix, fused fp16 prologue

#define B_ 2
#define H_ 16
#define S_ 2048
#define D_ 128

constexpr int BR      = 64;
constexpr int BC      = 64;
constexpr int THREADS = 128;

// smem row strides in 32-bit words; stride % 32 == 4 -> ldmatrix phases
// cover all 32 banks (conflict-free). Stage strides are %32==0.
constexpr int KSTW = 68;   // K tile row: 128 halfs + pad
constexpr int VSTW = 36;   // VT tile row: 64 halfs + pad

constexpr int KTILE_W = BC * KSTW;               // 4352 words / stage
constexpr int VTILE_W = D_ * VSTW;               // 4608 words / stage
constexpr int KSTAGES = 4;
constexpr int VSTAGES = 2;
constexpr int SM_V    = KSTAGES * KTILE_W;       // 17408
constexpr int SMEM_WORDS = KSTAGES * KTILE_W + VSTAGES * VTILE_W;  // 26624
constexpr int SMEM_BYTES = SMEM_WORDS * 4;       // 106496 B -> 2 CTAs/SM

constexpr int KV_ELEMS = B_ * H_ * S_ * D_;

__device__ __align__(16) __half g_kth[KV_ELEMS];   // K fp16 [bh][s][d]
__device__ __align__(16) __half g_vth[KV_ELEMS];   // V fp16 transposed [bh][d][s]

// ---------------------------------------------------------------------------
// Fused prologue (unchanged): V->fp16 transposed tile + K->fp16 slice.
// ---------------------------------------------------------------------------
__global__ void __launch_bounds__(256)
prep_kv_kernel(const float* __restrict__ v, const float4* __restrict__ k) {
    __shared__ __half tile[64][65];
    const int bh = blockIdx.z;
    const int s0 = blockIdx.x * 64;
    const int d0 = blockIdx.y * 64;
    const float* vp = v + (long)bh * S_ * D_;
    __half* vtp = g_vth + (long)bh * (long)D_ * S_;

    const int tx = threadIdx.x & 15;
    const int ty = threadIdx.x >> 4;
    #pragma unroll
    for (int p = 0; p < 4; ++p) {
        int si = ty + p * 16;
        float4 a = *(const float4*)(vp + (long)(s0 + si) * D_ + d0 + tx * 4);
        tile[si][tx * 4 + 0] = __float2half_rn(a.x);
        tile[si][tx * 4 + 1] = __float2half_rn(a.y);
        tile[si][tx * 4 + 2] = __float2half_rn(a.z);
        tile[si][tx * 4 + 3] = __float2half_rn(a.w);
    }
    {
        const long nblk = (long)gridDim.x * gridDim.y * gridDim.z;
        const long bid  = (long)(blockIdx.z * gridDim.y + blockIdx.y) * gridDim.x
                        + blockIdx.x;
        const long per  = (KV_ELEMS / 4) / nblk;
        uint2* kd = reinterpret_cast<uint2*>(g_kth);
        long i0 = bid * per;
        for (long i = i0 + threadIdx.x; i < i0 + per; i += 256) {
            float4 a = k[i];
            __half2 lo = __floats2half2_rn(a.x, a.y);
            __half2 hi = __floats2half2_rn(a.z, a.w);
            uint2 o;
            o.x = *(uint32_t*)&lo;
            o.y = *(uint32_t*)&hi;
            kd[i] = o;
        }
    }
    __syncthreads();
    const int lane = threadIdx.x & 31;
    const int w    = threadIdx.x >> 5;
    #pragma unroll
    for (int p = 0; p < 8; ++p) {
        int di = w + p * 8;
        __half2 h = __halves2half2(tile[2 * lane][di], tile[2 * lane + 1][di]);
        *(__half2*)(vtp + (long)(d0 + di) * S_ + s0 + 2 * lane) = h;
    }
}

// ---------------------------------------------------------------------------
__device__ __forceinline__ void mma_f16(float c[4],
                                        uint32_t a0, uint32_t a1, uint32_t a2, uint32_t a3,
                                        uint32_t b0, uint32_t b1) {
    asm volatile(
        "mma.sync.aligned.m16n8k16.row.col.f32.f16.f16.f32 "
        "{%0,%1,%2,%3}, {%4,%5,%6,%7}, {%8,%9}, {%0,%1,%2,%3};"
        : "+f"(c[0]), "+f"(c[1]), "+f"(c[2]), "+f"(c[3])
        : "r"(a0), "r"(a1), "r"(a2), "r"(a3), "r"(b0), "r"(b1));
}
__device__ __forceinline__ void ldsm4(uint32_t& r0, uint32_t& r1,
                                      uint32_t& r2, uint32_t& r3, uint32_t addr) {
    asm volatile("ldmatrix.sync.aligned.m8n8.x4.shared.b16 {%0,%1,%2,%3}, [%4];"
                 : "=r"(r0), "=r"(r1), "=r"(r2), "=r"(r3) : "r"(addr));
}
__device__ __forceinline__ void cp_async16(uint32_t dst, const void* src) {
    asm volatile("cp.async.cg.shared.global [%0], [%1], 16;" :: "r"(dst), "l"(src));
}
__device__ __forceinline__ uint32_t pack2(float a, float b) {
    __half2 h = __floats2half2_rn(a, b);
    return *(uint32_t*)&h;
}
__device__ __forceinline__ float ex2(float x) {
    float r;
    asm("ex2.approx.ftz.f32 %0, %1;" : "=f"(r) : "f"(x));
    return r;
}

__device__ __forceinline__ void load_k_tile(const __half* kg, uint32_t kdst, int tid) {
    #pragma unroll
    for (int it = 0; it < (BC * 16) / THREADS; ++it) {
        int i = tid + it * THREADS;
        int row = i >> 4, ch = i & 15;
        cp_async16(kdst + (uint32_t)(row * KSTW + ch * 4) * 4u, kg + row * D_ + ch * 8);
    }
}
__device__ __forceinline__ void load_v_tile(const __half* vtg, uint32_t vdst, int tid) {
    #pragma unroll
    for (int it = 0; it < (D_ * 8) / THREADS; ++it) {
        int i = tid + it * THREADS;
        int row = i >> 3, ch = i & 7;
        cp_async16(vdst + (uint32_t)(row * VSTW + ch * 4) * 4u, vtg + (long)row * S_ + ch * 8);
    }
}
#define COMMIT() asm volatile("cp.async.commit_group;")
#define WAIT1()  asm volatile("cp.async.wait_group 1;")

// S = Q K^T for one 16x64 warp-tile (zero-init + 32 LDSM + 64 MMA).
__device__ __forceinline__ void qk_block(float (&sacc)[8][4],
                                         const uint32_t (&qreg)[8][4], uint32_t ktb) {
    #pragma unroll
    for (int nt = 0; nt < 8; ++nt)
        sacc[nt][0] = sacc[nt][1] = sacc[nt][2] = sacc[nt][3] = 0.f;
    #pragma unroll
    for (int nt = 0; nt < 8; ++nt) {
        const uint32_t krow = ktb + (uint32_t)(nt * 8 * KSTW) * 4u;
        #pragma unroll
        for (int kp = 0; kp < 4; ++kp) {
            uint32_t b0, b1, b2, b3;
            ldsm4(b0, b1, b2, b3, krow + (uint32_t)(kp * 16) * 4u);
            mma_f16(sacc[nt], qreg[2*kp][0], qreg[2*kp][1], qreg[2*kp][2], qreg[2*kp][3], b0, b1);
            mma_f16(sacc[nt], qreg[2*kp+1][0], qreg[2*kp+1][1], qreg[2*kp+1][2], qreg[2*kp+1][3], b2, b3);
        }
    }
}

// mask + online softmax for one tile held in s[8][4]; produces P a-frags.
__device__ __forceinline__ void softmax_tile(float (&s)[8][4], int kvb, int wrow,
                                             int g, int c,
                                             float& m0, float& m1,
                                             float& l0, float& l1,
                                             float& a0, float& a1,
                                             uint32_t (&pa)[4][4]) {
    if (kvb + BC - 1 > wrow) {
        #pragma unroll
        for (int nt = 0; nt < 8; ++nt) {
            #pragma unroll
            for (int idx = 0; idx < 4; ++idx) {
                int col = kvb + nt * 8 + (c << 1) + (idx & 1);
                int row = wrow + g + ((idx >> 1) << 3);
                if (col > row) s[nt][idx] = -1e30f;
            }
        }
    }
    float tm0 = -1e30f, tm1 = -1e30f;
    #pragma unroll
    for (int nt = 0; nt < 8; ++nt) {
        tm0 = fmaxf(tm0, fmaxf(s[nt][0], s[nt][1]));
        tm1 = fmaxf(tm1, fmaxf(s[nt][2], s[nt][3]));
    }
    tm0 = fmaxf(tm0, __shfl_xor_sync(0xffffffffu, tm0, 1));
    tm0 = fmaxf(tm0, __shfl_xor_sync(0xffffffffu, tm0, 2));
    tm1 = fmaxf(tm1, __shfl_xor_sync(0xffffffffu, tm1, 1));
    tm1 = fmaxf(tm1, __shfl_xor_sync(0xffffffffu, tm1, 2));

    const float nm0 = fmaxf(m0, tm0), nm1 = fmaxf(m1, tm1);
    a0 = ex2(m0 - nm0); a1 = ex2(m1 - nm1);
    m0 = nm0; m1 = nm1;

    float ts0 = 0.f, ts1 = 0.f;
    #pragma unroll
    for (int nt = 0; nt < 8; ++nt) {
        float p00 = ex2(s[nt][0] - nm0);
        float p01 = ex2(s[nt][1] - nm0);
        float p10 = ex2(s[nt][2] - nm1);
        float p11 = ex2(s[nt][3] - nm1);
        ts0 += p00 + p01;
        ts1 += p10 + p11;
        if ((nt & 1) == 0) {
            pa[nt >> 1][0] = pack2(p00, p01);
            pa[nt >> 1][1] = pack2(p10, p11);
        } else {
            pa[nt >> 1][2] = pack2(p00, p01);
            pa[nt >> 1][3] = pack2(p10, p11);
        }
    }
    ts0 += __shfl_xor_sync(0xffffffffu, ts0, 1);
    ts0 += __shfl_xor_sync(0xffffffffu, ts0, 2);
    ts1 += __shfl_xor_sync(0xffffffffu, ts1, 1);
    ts1 += __shfl_xor_sync(0xffffffffu, ts1, 2);
    l0 = l0 * a0 + ts0;
    l1 = l1 * a1 + ts1;
}

// One skewed iteration: PV(j) [pacur] + QK(j+2) [-> scur] + softmax(j+1)
// [soth -> paoth]. Buffer roles swap between even/odd j at the call site,
// so no register copies are ever needed.
__device__ __forceinline__ void fa_iter(
    int j, int njt, int tid, int wrow, int g, int c,
    const __half* kg, const __half* vtg,
    uint32_t k_u32, uint32_t v_u32, uint32_t koff, uint32_t voff,
    const uint32_t (&qreg)[8][4], float (&oacc)[16][4],
    float (&scur)[8][4], float (&soth)[8][4],
    uint32_t (&pacur)[4][4], uint32_t (&paoth)[4][4],
    float& m0, float& m1, float& l0, float& l1, float& a0, float& a1)
{
    if (j + 3 < njt)
        load_k_tile(kg + (long)(j + 3) * BC * D_,
                    k_u32 + (uint32_t)(((j + 3) & 3) * KTILE_W) * 4u, tid);
    if (j + 1 < njt)
        load_v_tile(vtg + (j + 1) * BC,
                    v_u32 + (uint32_t)(((j + 1) & 1) * VTILE_W) * 4u, tid);
    COMMIT();
    WAIT1();            // all but newest group done: K(j+2), V(j) arrived
    __syncthreads();

    // 1. apply pending O rescale (factors from softmax(j))
    #pragma unroll
    for (int nt = 0; nt < 16; ++nt) {
        oacc[nt][0] *= a0; oacc[nt][1] *= a0;
        oacc[nt][2] *= a1; oacc[nt][3] *= a1;
    }

    // 2. PV(j): 32 LDSM + 64 MMA
    const uint32_t vtb = v_u32 + (uint32_t)((j & 1) * VTILE_W) * 4u + voff;
    #pragma unroll
    for (int nt = 0; nt < 16; ++nt) {
        const uint32_t vrow = vtb + (uint32_t)(nt * 8 * VSTW) * 4u;
        uint32_t b0, b1, b2, b3, b4, b5, b6, b7;
        ldsm4(b0, b1, b2, b3, vrow);
        ldsm4(b4, b5, b6, b7, vrow + 64u);
        mma_f16(oacc[nt], pacur[0][0], pacur[0][1], pacur[0][2], pacur[0][3], b0, b1);
        mma_f16(oacc[nt], pacur[1][0], pacur[1][1], pacur[1][2], pacur[1][3], b2, b3);
        mma_f16(oacc[nt], pacur[2][0], pacur[2][1], pacur[2][2], pacur[2][3], b4, b5);
        mma_f16(oacc[nt], pacur[3][0], pacur[3][1], pacur[3][2], pacur[3][3], b6, b7);
    }

    // 3. QK(j+2): independent MMA burst, overwrites the consumed buffer
    if (j + 2 < njt)
        qk_block(scur, qreg,
                 k_u32 + (uint32_t)(((j + 2) & 3) * KTILE_W) * 4u + koff);

    // 4. softmax(j+1): scalar chain, overlaps 2 & 3
    if (j + 1 < njt)
        softmax_tile(soth, (j + 1) * BC, wrow, g, c, m0, m1, l0, l1, a0, a1, paoth);

    __syncthreads();    // guard smem ring reuse
}

__global__ void __launch_bounds__(THREADS, 2)
fa_pp_kernel(const float* __restrict__ q, float* __restrict__ out) {
    extern __shared__ __align__(16) uint32_t smem[];

    const int tid  = threadIdx.x;
    const int lane = tid & 31;
    const int g    = lane >> 2;
    const int c    = lane & 3;
    const int r8   = lane & 7;
    const int s3   = (lane >> 3) & 1;
    const int s4   = lane >> 4;
    const int w    = tid >> 5;

    const int qt     = (int)(gridDim.x - 1) - (int)blockIdx.x;  // longest first
    const int bh     = blockIdx.y;
    const long base  = (long)bh * S_ * D_;
    const int q_base = qt * BR;
    const int njt    = qt + 1;
    const int wrow   = q_base + w * 16;

    // D^-0.5 * log2(e): softmax in base 2
    const float scale = 0.08838834764831845f * 1.4426950408889634f;

    const uint32_t smem_u32 = (uint32_t)__cvta_generic_to_shared(smem);
    const uint32_t k_u32    = smem_u32;
    const uint32_t v_u32    = smem_u32 + (uint32_t)SM_V * 4u;

    const uint32_t koff = (uint32_t)(r8 * KSTW + s4 * 8 + s3 * 4) * 4u;
    const uint32_t voff = (uint32_t)(r8 * VSTW + s4 * 8 + s3 * 4) * 4u;

    const __half* kg  = g_kth + base;    // [s][d]
    const __half* vtg = g_vth + base;    // [d][s]

    // ---- prologue loads: G0={K0}, G1={K1?} ----
    load_k_tile(kg, k_u32, tid);
    COMMIT();
    if (njt > 1) load_k_tile(kg + BC * D_, k_u32 + (uint32_t)KTILE_W * 4u, tid);
    COMMIT();

    // ---- Q: load, scale(+log2e), pack to half2 a-frags ----
    uint32_t qreg[8][4];
    {
        const float* qp = q + base;
        const long r0 = wrow + g, r1 = r0 + 8;
        #pragma unroll
        for (int ks = 0; ks < 8; ++ks) {
            int col = ks * 16 + 2 * c;
            qreg[ks][0] = pack2(qp[r0 * D_ + col]     * scale, qp[r0 * D_ + col + 1] * scale);
            qreg[ks][1] = pack2(qp[r1 * D_ + col]     * scale, qp[r1 * D_ + col + 1] * scale);
            qreg[ks][2] = pack2(qp[r0 * D_ + col + 8] * scale, qp[r0 * D_ + col + 9] * scale);
            qreg[ks][3] = pack2(qp[r1 * D_ + col + 8] * scale, qp[r1 * D_ + col + 9] * scale);
        }
    }

    float oacc[16][4];
    #pragma unroll
    for (int nt = 0; nt < 16; ++nt)
        oacc[nt][0] = oacc[nt][1] = oacc[nt][2] = oacc[nt][3] = 0.f;
    float m0 = -1e30f, m1 = -1e30f, l0 = 0.f, l1 = 0.f;
    float a0 = 0.f, a1 = 0.f;
    float sA[8][4], sB[8][4];
    uint32_t paA[4][4], paB[4][4];

    // ---- prologue compute: scores(0) -> sA, softmax(0) -> paA ----
    WAIT1();            // G0 (K0) complete
    __syncthreads();
    qk_block(sA, qreg, k_u32 + koff);
    softmax_tile(sA, 0, wrow, g, c, m0, m1, l0, l1, a0, a1, paA);
    // (a0,a1 = ex2(-inf) = 0; oacc is zero so iter-0 rescale is a no-op)

    // ---- G2 = {K2?, V0} ----
    if (njt > 2) load_k_tile(kg + 2 * BC * D_, k_u32 + (uint32_t)(2 * KTILE_W) * 4u, tid);
    load_v_tile(vtg, v_u32, tid);
    COMMIT();
    WAIT1();            // G1 (K1) complete
    __syncthreads();
    if (njt > 1)
        qk_block(sB, qreg, k_u32 + (uint32_t)KTILE_W * 4u + koff);   // scores(1)

    // =================== main loop, x2 unrolled ping-pong ===================
    int j = 0;
    for (; j + 1 < njt; j += 2) {
        // even j: PV uses paA; softmax(j+1) reads sB -> paB; QK(j+2) -> sA
        fa_iter(j,     njt, tid, wrow, g, c, kg, vtg, k_u32, v_u32, koff, voff,
                qreg, oacc, sA, sB, paA, paB, m0, m1, l0, l1, a0, a1);
        // odd j+1: roles swapped
        fa_iter(j + 1, njt, tid, wrow, g, c, kg, vtg, k_u32, v_u32, koff, voff,
                qreg, oacc, sB, sA, paB, paA, m0, m1, l0, l1, a0, a1);
    }
    if (j < njt)   // tail (even index)
        fa_iter(j, njt, tid, wrow, g, c, kg, vtg, k_u32, v_u32, koff, voff,
                qreg, oacc, sA, sB, paA, paB, m0, m1, l0, l1, a0, a1);

    // ---- epilogue: normalize and store ----
    const float inv0 = 1.f / l0, inv1 = 1.f / l1;
    float* op = out + base;
    const long r0 = wrow + g, r1 = r0 + 8;
    #pragma unroll
    for (int nt = 0; nt < 16; ++nt) {
        int col = nt * 8 + (c << 1);
        float2 o0 = make_float2(oacc[nt][0] * inv0, oacc[nt][1] * inv0);
        float2 o1 = make_float2(oacc[nt][2] * inv1, oacc[nt][3] * inv1);
        *(float2*)(op + r0 * D_ + col) = o0;
        *(float2*)(op + r1 * D_ + col) = o1;
    }
}

extern "C" void kernel_launch(void* const* d_in, const int* in_sizes, int n_in,
                              void* d_out, int out_size) {
    const float* q = (const float*)d_in[0];
    const float* k = (const float*)d_in[1];
    const float* v = (const float*)d_in[2];
    float* out = (float*)d_out;

    dim3 pgrid(S_ / 64, D_ / 64, B_ * H_);
    prep_kv_kernel<<<pgrid, 256>>>(v, (const float4*)k);

    cudaFuncSetAttribute(fa_pp_kernel,
                         cudaFuncAttributeMaxDynamicSharedMemorySize, SMEM_BYTES);
    dim3 grid(S_ / BR, B_ * H_);
    fa_pp_kernel<<<grid, THREADS, SMEM_BYTES>>>(q, out);
}